// round 2
// baseline (speedup 1.0000x reference)
#include <cuda_runtime.h>
#include <cstdint>

// Problem constants
#define BATCH 4
#define SEQ   2048
#define EMB   1024
#define NHEAD 16
#define HDIM  64
#define C3    3072
#define ROWS  8192   // BATCH*SEQ

// Scratch (device globals — allocation-free rule)
__device__ float g_qkv[(size_t)ROWS * C3];   // 96 MB
__device__ float g_y[(size_t)ROWS * EMB];    // 32 MB

// ---------------------------------------------------------------------------
// Tiled fp32 GEMM with bias:  C[M,N] = A[M,K] @ B[K,N] + bias[N]
// BM=BN=128, BK=16, 256 threads, 8x8 per thread.
// Requires M%128==0, N%128==0, K%16==0 (true for all our shapes).
// ---------------------------------------------------------------------------
__global__ __launch_bounds__(256, 2) void gemm_bias_kernel(
    const float* __restrict__ A, const float* __restrict__ B,
    const float* __restrict__ bias, float* __restrict__ C,
    int M, int N, int K)
{
    __shared__ float As[16][128];   // transposed A tile
    __shared__ float Bs[16][128];

    const int tid  = threadIdx.x;
    const int brow = blockIdx.y * 128;
    const int bcol = blockIdx.x * 128;
    const int tx = tid & 15;   // col group
    const int ty = tid >> 4;   // row group

    float acc[8][8];
#pragma unroll
    for (int i = 0; i < 8; i++)
#pragma unroll
        for (int j = 0; j < 8; j++) acc[i][j] = 0.f;

    for (int k0 = 0; k0 < K; k0 += 16) {
        // Load A tile 128x16 (512 float4, 2 per thread), store transposed
#pragma unroll
        for (int i = 0; i < 2; i++) {
            int s   = tid + i * 256;
            int row = s >> 2;
            int c4  = (s & 3) * 4;
            float4 v = *(const float4*)(A + (size_t)(brow + row) * K + k0 + c4);
            As[c4 + 0][row] = v.x;
            As[c4 + 1][row] = v.y;
            As[c4 + 2][row] = v.z;
            As[c4 + 3][row] = v.w;
        }
        // Load B tile 16x128
#pragma unroll
        for (int i = 0; i < 2; i++) {
            int s   = tid + i * 256;
            int row = s >> 5;
            int c4  = (s & 31) * 4;
            *(float4*)&Bs[row][c4] =
                *(const float4*)(B + (size_t)(k0 + row) * N + bcol + c4);
        }
        __syncthreads();

#pragma unroll
        for (int k = 0; k < 16; k++) {
            float a[8], b[8];
            *(float4*)&a[0] = *(float4*)&As[k][ty * 8];
            *(float4*)&a[4] = *(float4*)&As[k][ty * 8 + 4];
            *(float4*)&b[0] = *(float4*)&Bs[k][tx * 8];
            *(float4*)&b[4] = *(float4*)&Bs[k][tx * 8 + 4];
#pragma unroll
            for (int i = 0; i < 8; i++)
#pragma unroll
                for (int j = 0; j < 8; j++)
                    acc[i][j] += a[i] * b[j];
        }
        __syncthreads();
    }

    // Epilogue: bias + store
#pragma unroll
    for (int i = 0; i < 8; i++) {
        int row = brow + ty * 8 + i;
#pragma unroll
        for (int j = 0; j < 8; j += 4) {
            int col = bcol + tx * 8 + j;
            float4 o;
            o.x = acc[i][j + 0] + bias[col + 0];
            o.y = acc[i][j + 1] + bias[col + 1];
            o.z = acc[i][j + 2] + bias[col + 2];
            o.w = acc[i][j + 3] + bias[col + 3];
            *(float4*)(C + (size_t)row * N + col) = o;
        }
    }
}

// ---------------------------------------------------------------------------
// Flash attention (fp32, online softmax). One block = (q_tile, head, batch).
// Q tile 64 rows, K/V tiles 64 rows, D=64. 256 threads.
// Thread owns 4 rows (rg*4+i) x 4 cols (16*j+cg)  [col interleave 16 => all
// smem accesses bank-conflict-free with 68-float row pad].
// ---------------------------------------------------------------------------
#define APAD 68

__global__ __launch_bounds__(256) void attn_kernel(
    const float* __restrict__ qkv, float* __restrict__ y)
{
    extern __shared__ float sm[];
    float* Qs = sm;                 // [64][68]
    float* Ks = sm + 64 * APAD;
    float* Vs = sm + 2 * 64 * APAD;
    float* Ps = sm + 3 * 64 * APAD;

    const int tid = threadIdx.x;
    const int qt  = blockIdx.x;     // 0..31
    const int h   = blockIdx.y;     // 0..15
    const int b   = blockIdx.z;     // 0..3
    const int rg  = tid >> 4;       // 0..15
    const int cg  = tid & 15;       // 0..15

    // ---- load Q tile (64x64) ----
    const float* qbase = qkv + (size_t)(b * SEQ + qt * 64) * C3 + h * HDIM;
#pragma unroll
    for (int i = 0; i < 4; i++) {
        int s   = tid + i * 256;         // 0..1023 float4 slots
        int row = s >> 4;
        int c4  = (s & 15) * 4;
        *(float4*)&Qs[row * APAD + c4] =
            *(const float4*)(qbase + (size_t)row * C3 + c4);
    }

    float m[4], l[4], acc[4][4];
#pragma unroll
    for (int i = 0; i < 4; i++) {
        m[i] = -1e30f; l[i] = 0.f;
#pragma unroll
        for (int j = 0; j < 4; j++) acc[i][j] = 0.f;
    }

    for (int kt = 0; kt <= qt; kt++) {
        __syncthreads();   // prev iteration done with K/V

        // ---- load K and V tiles ----
        const float* kbase = qkv + (size_t)(b * SEQ + kt * 64) * C3 + EMB + h * HDIM;
#pragma unroll
        for (int i = 0; i < 4; i++) {
            int s   = tid + i * 256;
            int row = s >> 4;
            int c4  = (s & 15) * 4;
            *(float4*)&Ks[row * APAD + c4] =
                *(const float4*)(kbase + (size_t)row * C3 + c4);
            *(float4*)&Vs[row * APAD + c4] =
                *(const float4*)(kbase + EMB + (size_t)row * C3 + c4);
        }
        __syncthreads();

        // ---- S = Q K^T (thread: rows rg*4+i, cols 16*j+cg) ----
        float s4[4][4];
#pragma unroll
        for (int i = 0; i < 4; i++)
#pragma unroll
            for (int j = 0; j < 4; j++) s4[i][j] = 0.f;

        const float4* Q4 = (const float4*)Qs;
        const float4* K4 = (const float4*)Ks;
#pragma unroll
        for (int d4 = 0; d4 < 16; d4++) {
            float4 qv[4], kv[4];
#pragma unroll
            for (int i = 0; i < 4; i++) qv[i] = Q4[(rg * 4 + i) * (APAD/4) + d4];
#pragma unroll
            for (int j = 0; j < 4; j++) kv[j] = K4[(16 * j + cg) * (APAD/4) + d4];
#pragma unroll
            for (int i = 0; i < 4; i++)
#pragma unroll
                for (int j = 0; j < 4; j++)
                    s4[i][j] += qv[i].x * kv[j].x + qv[i].y * kv[j].y +
                                qv[i].z * kv[j].z + qv[i].w * kv[j].w;
        }

        // ---- scale + causal mask + online softmax ----
        float p[4][4];
#pragma unroll
        for (int i = 0; i < 4; i++) {
            int qi = qt * 64 + rg * 4 + i;
            float tmax = -1e30f;
#pragma unroll
            for (int j = 0; j < 4; j++) {
                float sv = s4[i][j] * 0.125f;
                int kj = kt * 64 + 16 * j + cg;
                if (kj > qi) sv = -1e30f;
                s4[i][j] = sv;
                tmax = fmaxf(tmax, sv);
            }
#pragma unroll
            for (int off = 1; off < 16; off <<= 1)
                tmax = fmaxf(tmax, __shfl_xor_sync(0xffffffffu, tmax, off));

            float mnew = fmaxf(m[i], tmax);
            float corr = __expf(m[i] - mnew);
            m[i] = mnew;
            float lsum = 0.f;
#pragma unroll
            for (int j = 0; j < 4; j++) {
                float pv = __expf(s4[i][j] - mnew);
                p[i][j] = pv;
                lsum += pv;
            }
#pragma unroll
            for (int off = 1; off < 16; off <<= 1)
                lsum += __shfl_xor_sync(0xffffffffu, lsum, off);
            l[i] = l[i] * corr + lsum;
#pragma unroll
            for (int j = 0; j < 4; j++) acc[i][j] *= corr;
        }

        // ---- write P to smem (scalar, cols 16*j+cg → conflict-free) ----
#pragma unroll
        for (int i = 0; i < 4; i++)
#pragma unroll
            for (int j = 0; j < 4; j++)
                Ps[(rg * 4 + i) * APAD + 16 * j + cg] = p[i][j];
        __syncthreads();

        // ---- O += P @ V (P vectorized over k; V scalar at cols 16*j+cg) ----
        const float4* P4 = (const float4*)Ps;
#pragma unroll 4
        for (int k4 = 0; k4 < 16; k4++) {
            float4 pr[4];
#pragma unroll
            for (int i = 0; i < 4; i++)
                pr[i] = P4[(rg * 4 + i) * (APAD/4) + k4];
#pragma unroll
            for (int kk = 0; kk < 4; kk++) {
                int k = k4 * 4 + kk;
                float pk[4];
                pk[0] = (&pr[0].x)[kk];
                pk[1] = (&pr[1].x)[kk];
                pk[2] = (&pr[2].x)[kk];
                pk[3] = (&pr[3].x)[kk];
#pragma unroll
                for (int j = 0; j < 4; j++) {
                    float vv = Vs[k * APAD + 16 * j + cg];
#pragma unroll
                    for (int i = 0; i < 4; i++)
                        acc[i][j] += pk[i] * vv;
                }
            }
        }
    }

    // ---- normalize + write y ----
#pragma unroll
    for (int i = 0; i < 4; i++) {
        float inv = 1.f / l[i];
        size_t row = (size_t)(b * SEQ + qt * 64 + rg * 4 + i);
#pragma unroll
        for (int j = 0; j < 4; j++)
            y[row * EMB + h * HDIM + 16 * j + cg] = acc[i][j] * inv;
    }
}

// ---------------------------------------------------------------------------
extern "C" void kernel_launch(void* const* d_in, const int* in_sizes, int n_in,
                              void* d_out, int out_size)
{
    const float* x      = (const float*)d_in[0];
    const float* W_attn = (const float*)d_in[1];
    const float* b_attn = (const float*)d_in[2];
    const float* W_proj = (const float*)d_in[3];
    const float* b_proj = (const float*)d_in[4];
    float* out = (float*)d_out;

    float *qkv, *ybuf;
    cudaGetSymbolAddress((void**)&qkv,  g_qkv);
    cudaGetSymbolAddress((void**)&ybuf, g_y);

    // 1) qkv = x @ W_attn + b_attn    [8192,1024]x[1024,3072]
    {
        dim3 grid(C3 / 128, ROWS / 128);
        gemm_bias_kernel<<<grid, 256>>>(x, W_attn, b_attn, qkv, ROWS, C3, EMB);
    }

    // 2) flash attention → y
    {
        static const int smem = 4 * 64 * APAD * sizeof(float);  // 69632 B
        cudaFuncSetAttribute(attn_kernel,
                             cudaFuncAttributeMaxDynamicSharedMemorySize, smem);
        dim3 grid(SEQ / 64, NHEAD, BATCH);
        attn_kernel<<<grid, 256, smem>>>(qkv, ybuf);
    }

    // 3) out = y @ W_proj + b_proj    [8192,1024]x[1024,1024]
    {
        dim3 grid(EMB / 128, ROWS / 128);
        gemm_bias_kernel<<<grid, 256>>>(ybuf, W_proj, b_proj, out, ROWS, EMB, EMB);
    }
}

// round 5
// speedup vs baseline: 1.6297x; 1.6297x over previous
#include <cuda_runtime.h>
#include <cstdint>

// Problem constants
#define BATCH 4
#define SEQ   2048
#define EMB   1024
#define NHEAD 16
#define HDIM  64
#define C3    3072
#define ROWS  8192   // BATCH*SEQ

// Scratch (device globals — allocation-free rule)
__device__ float g_qkv[(size_t)ROWS * C3];   // 96 MB
__device__ float g_y[(size_t)ROWS * EMB];    // 32 MB

__device__ __forceinline__ unsigned f2tf32(float f) {
    unsigned r;
    asm("cvt.rna.tf32.f32 %0, %1;" : "=r"(r) : "f"(f));
    return r;
}

// ---------------------------------------------------------------------------
// tf32 tensor-core GEMM with bias: C[M,N] = A[M,K] @ B[K,N] + bias[N]
// BM=BN=128, BK=32. 256 threads = 8 warps (2 m x 4 n), warp tile 64x32,
// per warp 4x4 grid of mma.sync.m16n8k8 tiles.
// Smem: As[m][k] stride 36 (frag banks 4*gid+tig: conflict-free),
//       Bs[k][n] stride 136 (frag banks gid+8*tig: conflict-free).
// ---------------------------------------------------------------------------
#define AS_STRIDE 36
#define BS_STRIDE 136

__global__ __launch_bounds__(256, 2) void gemm_tf32_kernel(
    const float* __restrict__ A, const float* __restrict__ B,
    const float* __restrict__ bias, float* __restrict__ C,
    int M, int N, int K)
{
    __shared__ unsigned As[128 * AS_STRIDE];  // 18432 B
    __shared__ unsigned Bs[32 * BS_STRIDE];   // 17408 B

    const int tid  = threadIdx.x;
    const int brow = blockIdx.y * 128;
    const int bcol = blockIdx.x * 128;

    const int warp   = tid >> 5;
    const int lane   = tid & 31;
    const int gid    = lane >> 2;   // 0..7
    const int tig    = lane & 3;    // 0..3
    const int warp_m = warp & 1;    // 0..1  (64-row slab)
    const int warp_n = warp >> 1;   // 0..3  (32-col slab)
    const int wm0    = warp_m * 64;
    const int wn0    = warp_n * 32;

    float acc[4][4][4];
#pragma unroll
    for (int i = 0; i < 4; i++)
#pragma unroll
        for (int j = 0; j < 4; j++)
#pragma unroll
            for (int r = 0; r < 4; r++) acc[i][j][r] = 0.f;

    for (int k0 = 0; k0 < K; k0 += 32) {
        // ---- load A tile 128x32 (1024 float4 -> 4 per thread), cvt to tf32 ----
#pragma unroll
        for (int i = 0; i < 4; i++) {
            int s   = tid + i * 256;
            int row = s >> 3;            // 8 float4 per 32-float row
            int c4  = (s & 7) * 4;
            float4 v = *(const float4*)(A + (size_t)(brow + row) * K + k0 + c4);
            unsigned* dst = &As[row * AS_STRIDE + c4];
            dst[0] = f2tf32(v.x); dst[1] = f2tf32(v.y);
            dst[2] = f2tf32(v.z); dst[3] = f2tf32(v.w);
        }
        // ---- load B tile 32x128 ----
#pragma unroll
        for (int i = 0; i < 4; i++) {
            int s   = tid + i * 256;
            int row = s >> 5;            // 32 float4 per 128-float row
            int c4  = (s & 31) * 4;
            float4 v = *(const float4*)(B + (size_t)(k0 + row) * N + bcol + c4);
            unsigned* dst = &Bs[row * BS_STRIDE + c4];
            dst[0] = f2tf32(v.x); dst[1] = f2tf32(v.y);
            dst[2] = f2tf32(v.z); dst[3] = f2tf32(v.w);
        }
        __syncthreads();

#pragma unroll
        for (int k8 = 0; k8 < 4; k8++) {
            const int kk = k8 * 8;
            unsigned a[4][4], b[4][2];
#pragma unroll
            for (int mi = 0; mi < 4; mi++) {
                int r0 = wm0 + mi * 16 + gid;
                a[mi][0] = As[(r0    ) * AS_STRIDE + kk + tig];
                a[mi][1] = As[(r0 + 8) * AS_STRIDE + kk + tig];
                a[mi][2] = As[(r0    ) * AS_STRIDE + kk + tig + 4];
                a[mi][3] = As[(r0 + 8) * AS_STRIDE + kk + tig + 4];
            }
#pragma unroll
            for (int ni = 0; ni < 4; ni++) {
                int c0 = wn0 + ni * 8 + gid;
                b[ni][0] = Bs[(kk + tig    ) * BS_STRIDE + c0];
                b[ni][1] = Bs[(kk + tig + 4) * BS_STRIDE + c0];
            }
#pragma unroll
            for (int mi = 0; mi < 4; mi++)
#pragma unroll
                for (int ni = 0; ni < 4; ni++) {
                    asm volatile(
                        "mma.sync.aligned.m16n8k8.row.col.f32.tf32.tf32.f32 "
                        "{%0,%1,%2,%3}, {%4,%5,%6,%7}, {%8,%9}, {%0,%1,%2,%3};\n"
                        : "+f"(acc[mi][ni][0]), "+f"(acc[mi][ni][1]),
                          "+f"(acc[mi][ni][2]), "+f"(acc[mi][ni][3])
                        : "r"(a[mi][0]), "r"(a[mi][1]), "r"(a[mi][2]), "r"(a[mi][3]),
                          "r"(b[ni][0]), "r"(b[ni][1]));
                }
        }
        __syncthreads();
    }

    // ---- epilogue: bias + store (c0,c1 -> row gid; c2,c3 -> row gid+8) ----
#pragma unroll
    for (int mi = 0; mi < 4; mi++) {
#pragma unroll
        for (int ni = 0; ni < 4; ni++) {
            int row0 = brow + wm0 + mi * 16 + gid;
            int col  = bcol + wn0 + ni * 8 + 2 * tig;
            float b0 = bias[col], b1 = bias[col + 1];
            float2 o0 = make_float2(acc[mi][ni][0] + b0, acc[mi][ni][1] + b1);
            float2 o1 = make_float2(acc[mi][ni][2] + b0, acc[mi][ni][3] + b1);
            *(float2*)(C + (size_t)row0 * N + col)       = o0;
            *(float2*)(C + (size_t)(row0 + 8) * N + col) = o1;
        }
    }
}

// ---------------------------------------------------------------------------
// Flash attention (fp32, online softmax). One block = (q_tile, head, batch).
// Q tile 64 rows, K/V tiles 64 rows, D=64. 256 threads.
// ---------------------------------------------------------------------------
#define APAD 68

__global__ __launch_bounds__(256) void attn_kernel(
    const float* __restrict__ qkv, float* __restrict__ y)
{
    extern __shared__ float sm[];
    float* Qs = sm;                 // [64][68]
    float* Ks = sm + 64 * APAD;
    float* Vs = sm + 2 * 64 * APAD;
    float* Ps = sm + 3 * 64 * APAD;

    const int tid = threadIdx.x;
    const int qt  = blockIdx.x;     // 0..31
    const int h   = blockIdx.y;     // 0..15
    const int b   = blockIdx.z;     // 0..3
    const int rg  = tid >> 4;       // 0..15
    const int cg  = tid & 15;       // 0..15

    const float* qbase = qkv + (size_t)(b * SEQ + qt * 64) * C3 + h * HDIM;
#pragma unroll
    for (int i = 0; i < 4; i++) {
        int s   = tid + i * 256;
        int row = s >> 4;
        int c4  = (s & 15) * 4;
        *(float4*)&Qs[row * APAD + c4] =
            *(const float4*)(qbase + (size_t)row * C3 + c4);
    }

    float m[4], l[4], acc[4][4];
#pragma unroll
    for (int i = 0; i < 4; i++) {
        m[i] = -1e30f; l[i] = 0.f;
#pragma unroll
        for (int j = 0; j < 4; j++) acc[i][j] = 0.f;
    }

    for (int kt = 0; kt <= qt; kt++) {
        __syncthreads();

        const float* kbase = qkv + (size_t)(b * SEQ + kt * 64) * C3 + EMB + h * HDIM;
#pragma unroll
        for (int i = 0; i < 4; i++) {
            int s   = tid + i * 256;
            int row = s >> 4;
            int c4  = (s & 15) * 4;
            *(float4*)&Ks[row * APAD + c4] =
                *(const float4*)(kbase + (size_t)row * C3 + c4);
            *(float4*)&Vs[row * APAD + c4] =
                *(const float4*)(kbase + EMB + (size_t)row * C3 + c4);
        }
        __syncthreads();

        float s4[4][4];
#pragma unroll
        for (int i = 0; i < 4; i++)
#pragma unroll
            for (int j = 0; j < 4; j++) s4[i][j] = 0.f;

        const float4* Q4 = (const float4*)Qs;
        const float4* K4 = (const float4*)Ks;
#pragma unroll
        for (int d4 = 0; d4 < 16; d4++) {
            float4 qv[4], kv[4];
#pragma unroll
            for (int i = 0; i < 4; i++) qv[i] = Q4[(rg * 4 + i) * (APAD/4) + d4];
#pragma unroll
            for (int j = 0; j < 4; j++) kv[j] = K4[(16 * j + cg) * (APAD/4) + d4];
#pragma unroll
            for (int i = 0; i < 4; i++)
#pragma unroll
                for (int j = 0; j < 4; j++)
                    s4[i][j] += qv[i].x * kv[j].x + qv[i].y * kv[j].y +
                                qv[i].z * kv[j].z + qv[i].w * kv[j].w;
        }

        float p[4][4];
#pragma unroll
        for (int i = 0; i < 4; i++) {
            int qi = qt * 64 + rg * 4 + i;
            float tmax = -1e30f;
#pragma unroll
            for (int j = 0; j < 4; j++) {
                float sv = s4[i][j] * 0.125f;
                int kj = kt * 64 + 16 * j + cg;
                if (kj > qi) sv = -1e30f;
                s4[i][j] = sv;
                tmax = fmaxf(tmax, sv);
            }
#pragma unroll
            for (int off = 1; off < 16; off <<= 1)
                tmax = fmaxf(tmax, __shfl_xor_sync(0xffffffffu, tmax, off));

            float mnew = fmaxf(m[i], tmax);
            float corr = __expf(m[i] - mnew);
            m[i] = mnew;
            float lsum = 0.f;
#pragma unroll
            for (int j = 0; j < 4; j++) {
                float pv = __expf(s4[i][j] - mnew);
                p[i][j] = pv;
                lsum += pv;
            }
#pragma unroll
            for (int off = 1; off < 16; off <<= 1)
                lsum += __shfl_xor_sync(0xffffffffu, lsum, off);
            l[i] = l[i] * corr + lsum;
#pragma unroll
            for (int j = 0; j < 4; j++) acc[i][j] *= corr;
        }

#pragma unroll
        for (int i = 0; i < 4; i++)
#pragma unroll
            for (int j = 0; j < 4; j++)
                Ps[(rg * 4 + i) * APAD + 16 * j + cg] = p[i][j];
        __syncthreads();

        const float4* P4 = (const float4*)Ps;
#pragma unroll 4
        for (int k4 = 0; k4 < 16; k4++) {
            float4 pr[4];
#pragma unroll
            for (int i = 0; i < 4; i++)
                pr[i] = P4[(rg * 4 + i) * (APAD/4) + k4];
#pragma unroll
            for (int kk = 0; kk < 4; kk++) {
                int k = k4 * 4 + kk;
                float pk[4];
                pk[0] = (&pr[0].x)[kk];
                pk[1] = (&pr[1].x)[kk];
                pk[2] = (&pr[2].x)[kk];
                pk[3] = (&pr[3].x)[kk];
#pragma unroll
                for (int j = 0; j < 4; j++) {
                    float vv = Vs[k * APAD + 16 * j + cg];
#pragma unroll
                    for (int i = 0; i < 4; i++)
                        acc[i][j] += pk[i] * vv;
                }
            }
        }
    }

#pragma unroll
    for (int i = 0; i < 4; i++) {
        float inv = 1.f / l[i];
        size_t row = (size_t)(b * SEQ + qt * 64 + rg * 4 + i);
#pragma unroll
        for (int j = 0; j < 4; j++)
            y[row * EMB + h * HDIM + 16 * j + cg] = acc[i][j] * inv;
    }
}

// ---------------------------------------------------------------------------
extern "C" void kernel_launch(void* const* d_in, const int* in_sizes, int n_in,
                              void* d_out, int out_size)
{
    const float* x      = (const float*)d_in[0];
    const float* W_attn = (const float*)d_in[1];
    const float* b_attn = (const float*)d_in[2];
    const float* W_proj = (const float*)d_in[3];
    const float* b_proj = (const float*)d_in[4];
    float* out = (float*)d_out;

    float *qkv, *ybuf;
    cudaGetSymbolAddress((void**)&qkv,  g_qkv);
    cudaGetSymbolAddress((void**)&ybuf, g_y);

    // 1) qkv = x @ W_attn + b_attn    [8192,1024]x[1024,3072]
    {
        dim3 grid(C3 / 128, ROWS / 128);
        gemm_tf32_kernel<<<grid, 256>>>(x, W_attn, b_attn, qkv, ROWS, C3, EMB);
    }

    // 2) flash attention -> y
    {
        static const int smem = 4 * 64 * APAD * sizeof(float);  // 69632 B
        cudaFuncSetAttribute(attn_kernel,
                             cudaFuncAttributeMaxDynamicSharedMemorySize, smem);
        dim3 grid(SEQ / 64, NHEAD, BATCH);
        attn_kernel<<<grid, 256, smem>>>(qkv, ybuf);
    }

    // 3) out = y @ W_proj + b_proj    [8192,1024]x[1024,1024]
    {
        dim3 grid(EMB / 128, ROWS / 128);
        gemm_tf32_kernel<<<grid, 256>>>(ybuf, W_proj, b_proj, out, ROWS, EMB, EMB);
    }
}

// round 7
// speedup vs baseline: 2.9230x; 1.7936x over previous
#include <cuda_runtime.h>
#include <cstdint>

// Problem constants
#define BATCH 4
#define SEQ   2048
#define EMB   1024
#define NHEAD 16
#define HDIM  64
#define C3    3072
#define ROWS  8192   // BATCH*SEQ

// Scratch (device globals — allocation-free rule)
__device__ float g_qkv[(size_t)ROWS * C3];   // 96 MB
__device__ float g_y[(size_t)ROWS * EMB];    // 32 MB

__device__ __forceinline__ unsigned f2tf32(float f) {
    unsigned r;
    asm("cvt.rna.tf32.f32 %0, %1;" : "=r"(r) : "f"(f));
    return r;
}

__device__ __forceinline__ void mma_tf32(
    float& c0, float& c1, float& c2, float& c3,
    unsigned a0, unsigned a1, unsigned a2, unsigned a3,
    unsigned b0, unsigned b1)
{
    asm volatile(
        "mma.sync.aligned.m16n8k8.row.col.f32.tf32.tf32.f32 "
        "{%0,%1,%2,%3}, {%4,%5,%6,%7}, {%8,%9}, {%0,%1,%2,%3};\n"
        : "+f"(c0), "+f"(c1), "+f"(c2), "+f"(c3)
        : "r"(a0), "r"(a1), "r"(a2), "r"(a3), "r"(b0), "r"(b1));
}

// ---------------------------------------------------------------------------
// tf32 tensor-core GEMM with bias: C[M,N] = A[M,K] @ B[K,N] + bias[N]
// (unchanged from R3 — tensor pipe 43.5%)
// ---------------------------------------------------------------------------
#define AS_STRIDE 36
#define BS_STRIDE 136

__global__ __launch_bounds__(256, 2) void gemm_tf32_kernel(
    const float* __restrict__ A, const float* __restrict__ B,
    const float* __restrict__ bias, float* __restrict__ C,
    int M, int N, int K)
{
    __shared__ unsigned As[128 * AS_STRIDE];
    __shared__ unsigned Bs[32 * BS_STRIDE];

    const int tid  = threadIdx.x;
    const int brow = blockIdx.y * 128;
    const int bcol = blockIdx.x * 128;

    const int warp   = tid >> 5;
    const int lane   = tid & 31;
    const int gid    = lane >> 2;
    const int tig    = lane & 3;
    const int wm0    = (warp & 1) * 64;
    const int wn0    = (warp >> 1) * 32;

    float acc[4][4][4];
#pragma unroll
    for (int i = 0; i < 4; i++)
#pragma unroll
        for (int j = 0; j < 4; j++)
#pragma unroll
            for (int r = 0; r < 4; r++) acc[i][j][r] = 0.f;

    for (int k0 = 0; k0 < K; k0 += 32) {
#pragma unroll
        for (int i = 0; i < 4; i++) {
            int s   = tid + i * 256;
            int row = s >> 3;
            int c4  = (s & 7) * 4;
            float4 v = *(const float4*)(A + (size_t)(brow + row) * K + k0 + c4);
            unsigned* dst = &As[row * AS_STRIDE + c4];
            dst[0] = f2tf32(v.x); dst[1] = f2tf32(v.y);
            dst[2] = f2tf32(v.z); dst[3] = f2tf32(v.w);
        }
#pragma unroll
        for (int i = 0; i < 4; i++) {
            int s   = tid + i * 256;
            int row = s >> 5;
            int c4  = (s & 31) * 4;
            float4 v = *(const float4*)(B + (size_t)(k0 + row) * N + bcol + c4);
            unsigned* dst = &Bs[row * BS_STRIDE + c4];
            dst[0] = f2tf32(v.x); dst[1] = f2tf32(v.y);
            dst[2] = f2tf32(v.z); dst[3] = f2tf32(v.w);
        }
        __syncthreads();

#pragma unroll
        for (int k8 = 0; k8 < 4; k8++) {
            const int kk = k8 * 8;
            unsigned a[4][4], b[4][2];
#pragma unroll
            for (int mi = 0; mi < 4; mi++) {
                int r0 = wm0 + mi * 16 + gid;
                a[mi][0] = As[(r0    ) * AS_STRIDE + kk + tig];
                a[mi][1] = As[(r0 + 8) * AS_STRIDE + kk + tig];
                a[mi][2] = As[(r0    ) * AS_STRIDE + kk + tig + 4];
                a[mi][3] = As[(r0 + 8) * AS_STRIDE + kk + tig + 4];
            }
#pragma unroll
            for (int ni = 0; ni < 4; ni++) {
                int c0 = wn0 + ni * 8 + gid;
                b[ni][0] = Bs[(kk + tig    ) * BS_STRIDE + c0];
                b[ni][1] = Bs[(kk + tig + 4) * BS_STRIDE + c0];
            }
#pragma unroll
            for (int mi = 0; mi < 4; mi++)
#pragma unroll
                for (int ni = 0; ni < 4; ni++)
                    mma_tf32(acc[mi][ni][0], acc[mi][ni][1],
                             acc[mi][ni][2], acc[mi][ni][3],
                             a[mi][0], a[mi][1], a[mi][2], a[mi][3],
                             b[ni][0], b[ni][1]);
        }
        __syncthreads();
    }

#pragma unroll
    for (int mi = 0; mi < 4; mi++) {
#pragma unroll
        for (int ni = 0; ni < 4; ni++) {
            int row0 = brow + wm0 + mi * 16 + gid;
            int col  = bcol + wn0 + ni * 8 + 2 * tig;
            float b0 = bias[col], b1 = bias[col + 1];
            float2 o0 = make_float2(acc[mi][ni][0] + b0, acc[mi][ni][1] + b1);
            float2 o1 = make_float2(acc[mi][ni][2] + b0, acc[mi][ni][3] + b1);
            *(float2*)(C + (size_t)row0 * N + col)       = o0;
            *(float2*)(C + (size_t)(row0 + 8) * N + col) = o1;
        }
    }
}

// ---------------------------------------------------------------------------
// Tensor-core flash attention (tf32 mma, online softmax).
// Block = (q_tile of 128 rows, head, batch). 256 threads = 8 warps.
// Warp w owns q-rows [16w, 16w+16) exclusively -> warp-local softmax.
// K/V tiles: 64 keys. Per warp: S = 8 n8-tiles, O = 8 n8-tiles over D=64.
// Smem strides: Q/K/P 68 (frag banks 4*gid+tig), V 72 (banks 8*tig+gid):
// all mma fragment loads bank-conflict-free.
// ---------------------------------------------------------------------------
#define QT      128
#define KT      64
#define QS_STR  68
#define KS_STR  68
#define VS_STR  72
#define PS_STR  68

__global__ __launch_bounds__(256, 2) void attn_mma_kernel(
    const float* __restrict__ qkv, float* __restrict__ y)
{
    extern __shared__ unsigned sm_u[];
    unsigned* Qs = sm_u;                              // [128][68]
    unsigned* Ks = Qs + QT * QS_STR;                  // [64][68]
    unsigned* Vs = Ks + KT * KS_STR;                  // [64][72]
    unsigned* Ps = Vs + KT * VS_STR;                  // [128][68]

    const int tid  = threadIdx.x;
    const int qt   = blockIdx.x;      // 0..15
    const int h    = blockIdx.y;
    const int b    = blockIdx.z;
    const int warp = tid >> 5;
    const int lane = tid & 31;
    const int gid  = lane >> 2;       // 0..7
    const int tig  = lane & 3;        // 0..3
    const int wq0  = warp * 16;       // warp's q-row base within tile

    // ---- load Q tile (128 x 64) as tf32 ----
    const float* qbase = qkv + (size_t)(b * SEQ + qt * QT) * C3 + h * HDIM;
#pragma unroll
    for (int i = 0; i < 8; i++) {
        int s   = tid + i * 256;
        int row = s >> 4;             // 16 float4 per 64-float row
        int c4  = (s & 15) * 4;
        float4 v = *(const float4*)(qbase + (size_t)row * C3 + c4);
        unsigned* dst = &Qs[row * QS_STR + c4];
        dst[0] = f2tf32(v.x); dst[1] = f2tf32(v.y);
        dst[2] = f2tf32(v.z); dst[3] = f2tf32(v.w);
    }

    float o[8][4];
    float m[2], l[2];
#pragma unroll
    for (int t = 0; t < 8; t++)
#pragma unroll
        for (int r = 0; r < 4; r++) o[t][r] = 0.f;
    m[0] = m[1] = -1e30f;
    l[0] = l[1] = 0.f;

    const int qrow0 = qt * QT + wq0 + gid;      // global q row (lower)
    const int kc_max = 2 * qt + 1;

    for (int kc = 0; kc <= kc_max; kc++) {
        __syncthreads();   // prev iter done with Ks/Vs (also covers Q load)

        // ---- load K,V tiles (64 x 64 each) as tf32 ----
        const float* kb = qkv + (size_t)(b * SEQ + kc * KT) * C3 + EMB + h * HDIM;
#pragma unroll
        for (int i = 0; i < 4; i++) {
            int s   = tid + i * 256;
            int row = s >> 4;
            int c4  = (s & 15) * 4;
            float4 kv = *(const float4*)(kb + (size_t)row * C3 + c4);
            float4 vv = *(const float4*)(kb + EMB + (size_t)row * C3 + c4);
            unsigned* dk = &Ks[row * KS_STR + c4];
            dk[0] = f2tf32(kv.x); dk[1] = f2tf32(kv.y);
            dk[2] = f2tf32(kv.z); dk[3] = f2tf32(kv.w);
            unsigned* dv = &Vs[row * VS_STR + c4];
            dv[0] = f2tf32(vv.x); dv[1] = f2tf32(vv.y);
            dv[2] = f2tf32(vv.z); dv[3] = f2tf32(vv.w);
        }
        __syncthreads();

        // ---- S = Q K^T : 8 n8-tiles x 8 k8-steps ----
        float s4[8][4];
#pragma unroll
        for (int t = 0; t < 8; t++)
#pragma unroll
            for (int r = 0; r < 4; r++) s4[t][r] = 0.f;

#pragma unroll
        for (int k8 = 0; k8 < 8; k8++) {
            const int kk = k8 * 8;
            unsigned a0 = Qs[(wq0 + gid    ) * QS_STR + kk + tig];
            unsigned a1 = Qs[(wq0 + gid + 8) * QS_STR + kk + tig];
            unsigned a2 = Qs[(wq0 + gid    ) * QS_STR + kk + tig + 4];
            unsigned a3 = Qs[(wq0 + gid + 8) * QS_STR + kk + tig + 4];
#pragma unroll
            for (int t = 0; t < 8; t++) {
                unsigned b0 = Ks[(t * 8 + gid) * KS_STR + kk + tig];
                unsigned b1 = Ks[(t * 8 + gid) * KS_STR + kk + tig + 4];
                mma_tf32(s4[t][0], s4[t][1], s4[t][2], s4[t][3],
                         a0, a1, a2, a3, b0, b1);
            }
        }

        // ---- scale + causal mask + online softmax (warp-local rows) ----
        const bool need_mask = (kc >= 2 * qt);
        float p[8][4];
#pragma unroll
        for (int half = 0; half < 2; half++) {
            const int qi = qrow0 + half * 8;
            float tmax = -1e30f;
#pragma unroll
            for (int t = 0; t < 8; t++) {
                float v0 = s4[t][2 * half]     * 0.125f;
                float v1 = s4[t][2 * half + 1] * 0.125f;
                if (need_mask) {
                    int kj = kc * KT + t * 8 + 2 * tig;
                    if (kj     > qi) v0 = -1e30f;
                    if (kj + 1 > qi) v1 = -1e30f;
                }
                s4[t][2 * half]     = v0;
                s4[t][2 * half + 1] = v1;
                tmax = fmaxf(tmax, fmaxf(v0, v1));
            }
            tmax = fmaxf(tmax, __shfl_xor_sync(0xffffffffu, tmax, 1));
            tmax = fmaxf(tmax, __shfl_xor_sync(0xffffffffu, tmax, 2));

            float mnew = fmaxf(m[half], tmax);
            float corr = __expf(m[half] - mnew);
            m[half] = mnew;
            float lsum = 0.f;
#pragma unroll
            for (int t = 0; t < 8; t++) {
                float p0 = __expf(s4[t][2 * half]     - mnew);
                float p1 = __expf(s4[t][2 * half + 1] - mnew);
                p[t][2 * half]     = p0;
                p[t][2 * half + 1] = p1;
                lsum += p0 + p1;
            }
            lsum += __shfl_xor_sync(0xffffffffu, lsum, 1);
            lsum += __shfl_xor_sync(0xffffffffu, lsum, 2);
            l[half] = l[half] * corr + lsum;
#pragma unroll
            for (int t = 0; t < 8; t++)
#pragma unroll
                for (int r = 0; r < 4; r++)
                    if ((r >> 1) == half) o[t][r] *= corr;
        }

        // ---- stage P in smem (tf32) for A-fragment reload ----
#pragma unroll
        for (int t = 0; t < 8; t++) {
            Ps[(wq0 + gid    ) * PS_STR + t * 8 + 2 * tig    ] = f2tf32(p[t][0]);
            Ps[(wq0 + gid    ) * PS_STR + t * 8 + 2 * tig + 1] = f2tf32(p[t][1]);
            Ps[(wq0 + gid + 8) * PS_STR + t * 8 + 2 * tig    ] = f2tf32(p[t][2]);
            Ps[(wq0 + gid + 8) * PS_STR + t * 8 + 2 * tig + 1] = f2tf32(p[t][3]);
        }
        __syncwarp();

        // ---- O += P @ V : 8 k8-steps (keys) x 8 n8-tiles (D) ----
#pragma unroll
        for (int k8 = 0; k8 < 8; k8++) {
            const int kk = k8 * 8;
            unsigned a0 = Ps[(wq0 + gid    ) * PS_STR + kk + tig];
            unsigned a1 = Ps[(wq0 + gid + 8) * PS_STR + kk + tig];
            unsigned a2 = Ps[(wq0 + gid    ) * PS_STR + kk + tig + 4];
            unsigned a3 = Ps[(wq0 + gid + 8) * PS_STR + kk + tig + 4];
#pragma unroll
            for (int t = 0; t < 8; t++) {
                unsigned b0 = Vs[(kk + tig    ) * VS_STR + t * 8 + gid];
                unsigned b1 = Vs[(kk + tig + 4) * VS_STR + t * 8 + gid];
                mma_tf32(o[t][0], o[t][1], o[t][2], o[t][3],
                         a0, a1, a2, a3, b0, b1);
            }
        }
    }

    // ---- normalize + write y ----
    const float inv0 = 1.f / l[0];
    const float inv1 = 1.f / l[1];
    float* yb = y + (size_t)(b * SEQ + qt * QT) * EMB + h * HDIM;
#pragma unroll
    for (int t = 0; t < 8; t++) {
        int col = t * 8 + 2 * tig;
        *(float2*)(yb + (size_t)(wq0 + gid    ) * EMB + col) =
            make_float2(o[t][0] * inv0, o[t][1] * inv0);
        *(float2*)(yb + (size_t)(wq0 + gid + 8) * EMB + col) =
            make_float2(o[t][2] * inv1, o[t][3] * inv1);
    }
}

// ---------------------------------------------------------------------------
extern "C" void kernel_launch(void* const* d_in, const int* in_sizes, int n_in,
                              void* d_out, int out_size)
{
    const float* x      = (const float*)d_in[0];
    const float* W_attn = (const float*)d_in[1];
    const float* b_attn = (const float*)d_in[2];
    const float* W_proj = (const float*)d_in[3];
    const float* b_proj = (const float*)d_in[4];
    float* out = (float*)d_out;

    float *qkv, *ybuf;
    cudaGetSymbolAddress((void**)&qkv,  g_qkv);
    cudaGetSymbolAddress((void**)&ybuf, g_y);

    // 1) qkv = x @ W_attn + b_attn
    {
        dim3 grid(C3 / 128, ROWS / 128);
        gemm_tf32_kernel<<<grid, 256>>>(x, W_attn, b_attn, qkv, ROWS, C3, EMB);
    }

    // 2) tensor-core flash attention -> y
    {
        const int smem = (QT * QS_STR + KT * KS_STR + KT * VS_STR + QT * PS_STR)
                         * (int)sizeof(unsigned);   // 105472 B
        cudaFuncSetAttribute(attn_mma_kernel,
                             cudaFuncAttributeMaxDynamicSharedMemorySize, smem);
        dim3 grid(SEQ / QT, NHEAD, BATCH);
        attn_mma_kernel<<<grid, 256, smem>>>(qkv, ybuf);
    }

    // 3) out = y @ W_proj + b_proj
    {
        dim3 grid(EMB / 128, ROWS / 128);
        gemm_tf32_kernel<<<grid, 256>>>(ybuf, W_proj, b_proj, out, ROWS, EMB, EMB);
    }
}

// round 9
// speedup vs baseline: 3.1842x; 1.0894x over previous
#include <cuda_runtime.h>
#include <cstdint>

// Problem constants
#define BATCH 4
#define SEQ   2048
#define EMB   1024
#define NHEAD 16
#define HDIM  64
#define C3    3072
#define ROWS  8192   // BATCH*SEQ

// Scratch (device globals — allocation-free rule). tf32 values stored as u32.
__device__ unsigned g_qkv[(size_t)ROWS * C3];   // 96 MB (tf32)
__device__ unsigned g_y[(size_t)ROWS * EMB];    // 32 MB (tf32)
__device__ unsigned g_xa[(size_t)ROWS * EMB];   // 32 MB (tf32 of x)
__device__ unsigned g_wa[(size_t)EMB * C3];     // 12 MB (tf32 of W_attn)
__device__ unsigned g_wp[(size_t)EMB * EMB];    //  4 MB (tf32 of W_proj)

__device__ __forceinline__ unsigned f2tf32(float f) {
    unsigned r;
    asm("cvt.rna.tf32.f32 %0, %1;" : "=r"(r) : "f"(f));
    return r;
}

__device__ __forceinline__ void mma_tf32(
    float& c0, float& c1, float& c2, float& c3,
    unsigned a0, unsigned a1, unsigned a2, unsigned a3,
    unsigned b0, unsigned b1)
{
    asm volatile(
        "mma.sync.aligned.m16n8k8.row.col.f32.tf32.tf32.f32 "
        "{%0,%1,%2,%3}, {%4,%5,%6,%7}, {%8,%9}, {%0,%1,%2,%3};\n"
        : "+f"(c0), "+f"(c1), "+f"(c2), "+f"(c3)
        : "r"(a0), "r"(a1), "r"(a2), "r"(a3), "r"(b0), "r"(b1));
}

__device__ __forceinline__ void cp_async16(unsigned saddr, const void* g) {
    asm volatile("cp.async.cg.shared.global [%0], [%1], 16;\n"
                 :: "r"(saddr), "l"(g));
}
__device__ __forceinline__ void cp_commit() {
    asm volatile("cp.async.commit_group;\n");
}
template <int N>
__device__ __forceinline__ void cp_wait() {
    asm volatile("cp.async.wait_group %0;\n" :: "n"(N));
}

// ---------------------------------------------------------------------------
// One-time RNA tf32 conversion (fp32 -> tf32-in-u32)
// ---------------------------------------------------------------------------
__global__ void cvt_tf32_kernel(const float4* __restrict__ in,
                                uint4* __restrict__ out, int n4)
{
    int i = blockIdx.x * blockDim.x + threadIdx.x;
    if (i < n4) {
        float4 v = in[i];
        out[i] = make_uint4(f2tf32(v.x), f2tf32(v.y), f2tf32(v.z), f2tf32(v.w));
    }
}

// ---------------------------------------------------------------------------
// tf32 tensor-core GEMM with bias, cp.async 2-stage pipeline.
// C[M,N] = A[M,K] @ B[K,N] + bias[N].  A,B pre-converted tf32 (u32).
// BM=BN=128, BK=32. 256 threads = 8 warps (2m x 4n), warp tile 64x32.
// OUT_TF32: epilogue emits tf32-in-u32 instead of fp32.
// ---------------------------------------------------------------------------
#define AS_STRIDE 36
#define BS_STRIDE 136
#define ASZ (128 * AS_STRIDE)
#define BSZ (32 * BS_STRIDE)
#define GEMM_SMEM (2 * (ASZ + BSZ) * (int)sizeof(unsigned))   // 71680 B

template <bool OUT_TF32>
__global__ __launch_bounds__(256, 2) void gemm_tf32_cp_kernel(
    const unsigned* __restrict__ A, const unsigned* __restrict__ B,
    const float* __restrict__ bias, void* __restrict__ Cout,
    int M, int N, int K)
{
    extern __shared__ unsigned smem[];

    const int tid  = threadIdx.x;
    const int brow = blockIdx.y * 128;
    const int bcol = blockIdx.x * 128;

    const int warp = tid >> 5;
    const int lane = tid & 31;
    const int gid  = lane >> 2;
    const int tig  = lane & 3;
    const int wm0  = (warp & 1) * 64;
    const int wn0  = (warp >> 1) * 32;

    // Per-thread cp.async chunk coordinates (4 chunks A + 4 chunks B)
    int a_row[4], a_c4[4], b_row[4], b_c4[4];
#pragma unroll
    for (int i = 0; i < 4; i++) {
        int s = tid + i * 256;
        a_row[i] = s >> 3;  a_c4[i] = (s & 7) * 4;    // A: 8 chunks / row of 32
        b_row[i] = s >> 5;  b_c4[i] = (s & 31) * 4;   // B: 32 chunks / row of 128
    }

    float acc[4][4][4];
#pragma unroll
    for (int i = 0; i < 4; i++)
#pragma unroll
        for (int j = 0; j < 4; j++)
#pragma unroll
            for (int r = 0; r < 4; r++) acc[i][j][r] = 0.f;

    const int T = K >> 5;   // BK=32 steps

    auto issue = [&](int t, int stage) {
        unsigned* As = smem + stage * (ASZ + BSZ);
        unsigned* Bs = As + ASZ;
        const int k0 = t << 5;
#pragma unroll
        for (int i = 0; i < 4; i++) {
            unsigned sa = (unsigned)__cvta_generic_to_shared(
                &As[a_row[i] * AS_STRIDE + a_c4[i]]);
            cp_async16(sa, A + (size_t)(brow + a_row[i]) * K + k0 + a_c4[i]);
        }
#pragma unroll
        for (int i = 0; i < 4; i++) {
            unsigned sb = (unsigned)__cvta_generic_to_shared(
                &Bs[b_row[i] * BS_STRIDE + b_c4[i]]);
            cp_async16(sb, B + (size_t)(k0 + b_row[i]) * N + bcol + b_c4[i]);
        }
        cp_commit();
    };

    issue(0, 0);

    for (int t = 0; t < T; t++) {
        const int cur = t & 1;
        if (t + 1 < T) {
            issue(t + 1, cur ^ 1);
            cp_wait<1>();
        } else {
            cp_wait<0>();
        }
        __syncthreads();

        unsigned* As = smem + cur * (ASZ + BSZ);
        unsigned* Bs = As + ASZ;

#pragma unroll
        for (int k8 = 0; k8 < 4; k8++) {
            const int kk = k8 * 8;
            unsigned a[4][4], b[4][2];
#pragma unroll
            for (int mi = 0; mi < 4; mi++) {
                int r0 = wm0 + mi * 16 + gid;
                a[mi][0] = As[(r0    ) * AS_STRIDE + kk + tig];
                a[mi][1] = As[(r0 + 8) * AS_STRIDE + kk + tig];
                a[mi][2] = As[(r0    ) * AS_STRIDE + kk + tig + 4];
                a[mi][3] = As[(r0 + 8) * AS_STRIDE + kk + tig + 4];
            }
#pragma unroll
            for (int ni = 0; ni < 4; ni++) {
                int c0 = wn0 + ni * 8 + gid;
                b[ni][0] = Bs[(kk + tig    ) * BS_STRIDE + c0];
                b[ni][1] = Bs[(kk + tig + 4) * BS_STRIDE + c0];
            }
#pragma unroll
            for (int mi = 0; mi < 4; mi++)
#pragma unroll
                for (int ni = 0; ni < 4; ni++)
                    mma_tf32(acc[mi][ni][0], acc[mi][ni][1],
                             acc[mi][ni][2], acc[mi][ni][3],
                             a[mi][0], a[mi][1], a[mi][2], a[mi][3],
                             b[ni][0], b[ni][1]);
        }
        __syncthreads();
    }

    // ---- epilogue: bias + store ----
#pragma unroll
    for (int mi = 0; mi < 4; mi++) {
#pragma unroll
        for (int ni = 0; ni < 4; ni++) {
            int row0 = brow + wm0 + mi * 16 + gid;
            int col  = bcol + wn0 + ni * 8 + 2 * tig;
            float b0 = bias[col], b1 = bias[col + 1];
            float v00 = acc[mi][ni][0] + b0, v01 = acc[mi][ni][1] + b1;
            float v10 = acc[mi][ni][2] + b0, v11 = acc[mi][ni][3] + b1;
            if (OUT_TF32) {
                unsigned* C = (unsigned*)Cout;
                *(uint2*)(C + (size_t)row0 * N + col) =
                    make_uint2(f2tf32(v00), f2tf32(v01));
                *(uint2*)(C + (size_t)(row0 + 8) * N + col) =
                    make_uint2(f2tf32(v10), f2tf32(v11));
            } else {
                float* C = (float*)Cout;
                *(float2*)(C + (size_t)row0 * N + col)       = make_float2(v00, v01);
                *(float2*)(C + (size_t)(row0 + 8) * N + col) = make_float2(v10, v11);
            }
        }
    }
}

// ---------------------------------------------------------------------------
// Tensor-core flash attention (tf32 mma, online softmax).
// qkv arrives pre-converted tf32 (u32); y is written tf32 (u32).
// Block = (q_tile 128 rows, head, batch). 8 warps, warp-local softmax.
// ---------------------------------------------------------------------------
#define QT      128
#define KT      64
#define QS_STR  68
#define KS_STR  68
#define VS_STR  72
#define PS_STR  68

__global__ __launch_bounds__(256, 2) void attn_mma_kernel(
    const unsigned* __restrict__ qkv, unsigned* __restrict__ y)
{
    extern __shared__ unsigned sm_u[];
    unsigned* Qs = sm_u;                              // [128][68]
    unsigned* Ks = Qs + QT * QS_STR;                  // [64][68]
    unsigned* Vs = Ks + KT * KS_STR;                  // [64][72]
    unsigned* Ps = Vs + KT * VS_STR;                  // [128][68]

    const int tid  = threadIdx.x;
    const int qt   = blockIdx.x;
    const int h    = blockIdx.y;
    const int b    = blockIdx.z;
    const int warp = tid >> 5;
    const int lane = tid & 31;
    const int gid  = lane >> 2;
    const int tig  = lane & 3;
    const int wq0  = warp * 16;

    // ---- load Q tile (128 x 64) ----
    const unsigned* qbase = qkv + (size_t)(b * SEQ + qt * QT) * C3 + h * HDIM;
#pragma unroll
    for (int i = 0; i < 8; i++) {
        int s   = tid + i * 256;
        int row = s >> 4;
        int c4  = (s & 15) * 4;
        *(uint4*)&Qs[row * QS_STR + c4] =
            *(const uint4*)(qbase + (size_t)row * C3 + c4);
    }

    float o[8][4];
    float m[2], l[2];
#pragma unroll
    for (int t = 0; t < 8; t++)
#pragma unroll
        for (int r = 0; r < 4; r++) o[t][r] = 0.f;
    m[0] = m[1] = -1e30f;
    l[0] = l[1] = 0.f;

    const int qrow0 = qt * QT + wq0 + gid;
    const int kc_max = 2 * qt + 1;

    for (int kc = 0; kc <= kc_max; kc++) {
        __syncthreads();

        const unsigned* kb = qkv + (size_t)(b * SEQ + kc * KT) * C3 + EMB + h * HDIM;
#pragma unroll
        for (int i = 0; i < 4; i++) {
            int s   = tid + i * 256;
            int row = s >> 4;
            int c4  = (s & 15) * 4;
            *(uint4*)&Ks[row * KS_STR + c4] =
                *(const uint4*)(kb + (size_t)row * C3 + c4);
            *(uint4*)&Vs[row * VS_STR + c4] =
                *(const uint4*)(kb + EMB + (size_t)row * C3 + c4);
        }
        __syncthreads();

        // ---- S = Q K^T ----
        float s4[8][4];
#pragma unroll
        for (int t = 0; t < 8; t++)
#pragma unroll
            for (int r = 0; r < 4; r++) s4[t][r] = 0.f;

#pragma unroll
        for (int k8 = 0; k8 < 8; k8++) {
            const int kk = k8 * 8;
            unsigned a0 = Qs[(wq0 + gid    ) * QS_STR + kk + tig];
            unsigned a1 = Qs[(wq0 + gid + 8) * QS_STR + kk + tig];
            unsigned a2 = Qs[(wq0 + gid    ) * QS_STR + kk + tig + 4];
            unsigned a3 = Qs[(wq0 + gid + 8) * QS_STR + kk + tig + 4];
#pragma unroll
            for (int t = 0; t < 8; t++) {
                unsigned b0 = Ks[(t * 8 + gid) * KS_STR + kk + tig];
                unsigned b1 = Ks[(t * 8 + gid) * KS_STR + kk + tig + 4];
                mma_tf32(s4[t][0], s4[t][1], s4[t][2], s4[t][3],
                         a0, a1, a2, a3, b0, b1);
            }
        }

        // ---- scale + causal mask + online softmax ----
        const bool need_mask = (kc >= 2 * qt);
        float p[8][4];
#pragma unroll
        for (int half = 0; half < 2; half++) {
            const int qi = qrow0 + half * 8;
            float tmax = -1e30f;
#pragma unroll
            for (int t = 0; t < 8; t++) {
                float v0 = s4[t][2 * half]     * 0.125f;
                float v1 = s4[t][2 * half + 1] * 0.125f;
                if (need_mask) {
                    int kj = kc * KT + t * 8 + 2 * tig;
                    if (kj     > qi) v0 = -1e30f;
                    if (kj + 1 > qi) v1 = -1e30f;
                }
                s4[t][2 * half]     = v0;
                s4[t][2 * half + 1] = v1;
                tmax = fmaxf(tmax, fmaxf(v0, v1));
            }
            tmax = fmaxf(tmax, __shfl_xor_sync(0xffffffffu, tmax, 1));
            tmax = fmaxf(tmax, __shfl_xor_sync(0xffffffffu, tmax, 2));

            float mnew = fmaxf(m[half], tmax);
            float corr = __expf(m[half] - mnew);
            m[half] = mnew;
            float lsum = 0.f;
#pragma unroll
            for (int t = 0; t < 8; t++) {
                float p0 = __expf(s4[t][2 * half]     - mnew);
                float p1 = __expf(s4[t][2 * half + 1] - mnew);
                p[t][2 * half]     = p0;
                p[t][2 * half + 1] = p1;
                lsum += p0 + p1;
            }
            lsum += __shfl_xor_sync(0xffffffffu, lsum, 1);
            lsum += __shfl_xor_sync(0xffffffffu, lsum, 2);
            l[half] = l[half] * corr + lsum;
#pragma unroll
            for (int t = 0; t < 8; t++)
#pragma unroll
                for (int r = 0; r < 4; r++)
                    if ((r >> 1) == half) o[t][r] *= corr;
        }

        // ---- stage P (tf32) ----
#pragma unroll
        for (int t = 0; t < 8; t++) {
            Ps[(wq0 + gid    ) * PS_STR + t * 8 + 2 * tig    ] = f2tf32(p[t][0]);
            Ps[(wq0 + gid    ) * PS_STR + t * 8 + 2 * tig + 1] = f2tf32(p[t][1]);
            Ps[(wq0 + gid + 8) * PS_STR + t * 8 + 2 * tig    ] = f2tf32(p[t][2]);
            Ps[(wq0 + gid + 8) * PS_STR + t * 8 + 2 * tig + 1] = f2tf32(p[t][3]);
        }
        __syncwarp();

        // ---- O += P @ V ----
#pragma unroll
        for (int k8 = 0; k8 < 8; k8++) {
            const int kk = k8 * 8;
            unsigned a0 = Ps[(wq0 + gid    ) * PS_STR + kk + tig];
            unsigned a1 = Ps[(wq0 + gid + 8) * PS_STR + kk + tig];
            unsigned a2 = Ps[(wq0 + gid    ) * PS_STR + kk + tig + 4];
            unsigned a3 = Ps[(wq0 + gid + 8) * PS_STR + kk + tig + 4];
#pragma unroll
            for (int t = 0; t < 8; t++) {
                unsigned b0 = Vs[(kk + tig    ) * VS_STR + t * 8 + gid];
                unsigned b1 = Vs[(kk + tig + 4) * VS_STR + t * 8 + gid];
                mma_tf32(o[t][0], o[t][1], o[t][2], o[t][3],
                         a0, a1, a2, a3, b0, b1);
            }
        }
    }

    // ---- normalize + write y as tf32 ----
    const float inv0 = 1.f / l[0];
    const float inv1 = 1.f / l[1];
    unsigned* yb = y + (size_t)(b * SEQ + qt * QT) * EMB + h * HDIM;
#pragma unroll
    for (int t = 0; t < 8; t++) {
        int col = t * 8 + 2 * tig;
        *(uint2*)(yb + (size_t)(wq0 + gid    ) * EMB + col) =
            make_uint2(f2tf32(o[t][0] * inv0), f2tf32(o[t][1] * inv0));
        *(uint2*)(yb + (size_t)(wq0 + gid + 8) * EMB + col) =
            make_uint2(f2tf32(o[t][2] * inv1), f2tf32(o[t][3] * inv1));
    }
}

// ---------------------------------------------------------------------------
extern "C" void kernel_launch(void* const* d_in, const int* in_sizes, int n_in,
                              void* d_out, int out_size)
{
    const float* x      = (const float*)d_in[0];
    const float* W_attn = (const float*)d_in[1];
    const float* b_attn = (const float*)d_in[2];
    const float* W_proj = (const float*)d_in[3];
    const float* b_proj = (const float*)d_in[4];
    float* out = (float*)d_out;

    unsigned *qkv, *ybuf, *xa, *wa, *wp;
    cudaGetSymbolAddress((void**)&qkv,  g_qkv);
    cudaGetSymbolAddress((void**)&ybuf, g_y);
    cudaGetSymbolAddress((void**)&xa,   g_xa);
    cudaGetSymbolAddress((void**)&wa,   g_wa);
    cudaGetSymbolAddress((void**)&wp,   g_wp);

    // 0) one-time RNA tf32 conversions
    {
        int n4x = ROWS * EMB / 4;
        cvt_tf32_kernel<<<(n4x + 255) / 256, 256>>>((const float4*)x, (uint4*)xa, n4x);
        int n4a = EMB * C3 / 4;
        cvt_tf32_kernel<<<(n4a + 255) / 256, 256>>>((const float4*)W_attn, (uint4*)wa, n4a);
        int n4p = EMB * EMB / 4;
        cvt_tf32_kernel<<<(n4p + 255) / 256, 256>>>((const float4*)W_proj, (uint4*)wp, n4p);
    }

    // 1) qkv(tf32) = x @ W_attn + b_attn
    {
        cudaFuncSetAttribute(gemm_tf32_cp_kernel<true>,
                             cudaFuncAttributeMaxDynamicSharedMemorySize, GEMM_SMEM);
        dim3 grid(C3 / 128, ROWS / 128);
        gemm_tf32_cp_kernel<true><<<grid, 256, GEMM_SMEM>>>(
            xa, wa, b_attn, qkv, ROWS, C3, EMB);
    }

    // 2) tensor-core flash attention -> y(tf32)
    {
        const int smem = (QT * QS_STR + KT * KS_STR + KT * VS_STR + QT * PS_STR)
                         * (int)sizeof(unsigned);   // 105472 B
        cudaFuncSetAttribute(attn_mma_kernel,
                             cudaFuncAttributeMaxDynamicSharedMemorySize, smem);
        dim3 grid(SEQ / QT, NHEAD, BATCH);
        attn_mma_kernel<<<grid, 256, smem>>>(qkv, ybuf);
    }

    // 3) out = y @ W_proj + b_proj
    {
        cudaFuncSetAttribute(gemm_tf32_cp_kernel<false>,
                             cudaFuncAttributeMaxDynamicSharedMemorySize, GEMM_SMEM);
        dim3 grid(EMB / 128, ROWS / 128);
        gemm_tf32_cp_kernel<false><<<grid, 256, GEMM_SMEM>>>(
            ybuf, wp, b_proj, out, ROWS, EMB, EMB);
    }
}